// round 10
// baseline (speedup 1.0000x reference)
#include <cuda_runtime.h>
#include <math.h>
#include <stdint.h>

#define Bn 4
#define Sn 2048
#define Dn 1024
#define Hn 16
#define DKn 64
#define Mn (Bn*Sn)   /* 8192 */
#define LD 68        /* smem row stride: Q/K tiles (row-pattern conflict-free) */
#define LDV 72       /* smem row stride: V tile (column-pattern conflict-free) */
#define QT 128       /* q-tile rows per CTA in flash attention */

// Scratch (device globals: allocation-free per harness rules)
// g_Q: tf32-rounded AND pre-scaled by 1/sqrt(DK); g_K/g_V: tf32-rounded.
__device__ float g_Q[Bn*Hn*Sn*DKn];
__device__ float g_K[Bn*Hn*Sn*DKn];
__device__ float g_V[Bn*Hn*Sn*DKn];
__device__ float g_ctx[Mn*Dn];

__device__ __forceinline__ uint32_t f2tf(float f) {
    uint32_t u;
    asm("cvt.rna.tf32.f32 %0, %1;" : "=r"(u) : "f"(f));
    return u;
}
__device__ __forceinline__ float tf32r(float f) { return __uint_as_float(f2tf(f)); }

__device__ __forceinline__ uint32_t s2u(const void* p) {
    return (uint32_t)__cvta_generic_to_shared(p);
}

#define CP16(dst_u32, src_ptr) asm volatile( \
    "cp.async.cg.shared.global [%0], [%1], 16;\n" :: "r"(dst_u32), "l"(src_ptr))
#define CP_COMMIT() asm volatile("cp.async.commit_group;\n" ::: "memory")
#define CP_WAIT(n)  asm volatile("cp.async.wait_group %0;\n" :: "n"(n) : "memory")

#define MMA_TF32(c, a, b) asm volatile( \
    "mma.sync.aligned.m16n8k8.row.col.f32.tf32.tf32.f32 " \
    "{%0,%1,%2,%3}, {%4,%5,%6,%7}, {%8,%9}, {%0,%1,%2,%3};\n" \
    : "+f"((c)[0]), "+f"((c)[1]), "+f"((c)[2]), "+f"((c)[3]) \
    : "r"((a)[0]), "r"((a)[1]), "r"((a)[2]), "r"((a)[3]), \
      "r"((b)[0]), "r"((b)[1]))

// ---------------------------------------------------------------------------
// tf32 tensor-core GEMM (R8-proven core). Epilogue now emits tf32-rounded
// (and, for Q, pre-scaled) values for the split destinations so flash can
// consume them raw via cp.async.
// ---------------------------------------------------------------------------
__device__ __forceinline__ void storeAfrag(uint32_t* sA, int arow, int k4, float4 v) {
    const int kt  = k4 >> 3;
    const int reg = (((arow & 15) >= 8) ? 1 : 0) | ((k4 & 4) ? 2 : 0);
    const int a7  = arow & 7;
    const int swz = ((a7 >> 1) & 3) << 2;
    const int base = (((arow >> 4) * 2 + kt) << 7) + (a7 << 4) + reg;
    sA[(base + 0)  ^ swz] = f2tf(v.x);
    sA[(base + 4)  ^ swz] = f2tf(v.y);
    sA[(base + 8)  ^ swz] = f2tf(v.z);
    sA[(base + 12) ^ swz] = f2tf(v.w);
}

__device__ __forceinline__ void storeBfrag(uint32_t* sB, int krow, int n4, float4 v) {
    const int kt    = krow >> 3;
    const int reg   = ((krow & 7) >= 4) ? 1 : 0;
    const int ntile = (n4 >> 3) * 2 + kt;
    const int swz   = ((ntile & 3) << 1) | (((ntile >> 2) & 3) << 3);
    const int base  = ntile * 64 + (n4 & 7) * 8 + (krow & 3) * 2 + reg;
    sB[(base + 0)  ^ swz] = f2tf(v.x);
    sB[(base + 8)  ^ swz] = f2tf(v.y);
    sB[(base + 16) ^ swz] = f2tf(v.z);
    sB[(base + 24) ^ swz] = f2tf(v.w);
}

__global__ __launch_bounds__(256) void gemm_tf32(
    const float* __restrict__ Ain, const float* __restrict__ W,
    const float* __restrict__ bias, float* __restrict__ OutP, int dst)
{
    __shared__ uint32_t sA[2][2048];
    __shared__ uint32_t sB[2][2048];

    const int tid  = threadIdx.x;
    const int bx   = blockIdx.x;
    const int by   = blockIdx.y;
    const int wid  = tid >> 5;
    const int lane = tid & 31;
    const int wm   = wid & 3;
    const int wn   = wid >> 2;
    const int gid  = lane >> 2;
    const int tig  = lane & 3;
    const int la   = (lane << 2) ^ (((lane >> 3) & 3) << 2);

    float* Out;
    bool   split;
    if      (dst == 0) { Out = g_Q;  split = true;  }
    else if (dst == 1) { Out = g_K;  split = true;  }
    else if (dst == 2) { Out = g_V;  split = true;  }
    else               { Out = OutP; split = false; }
    const float* A = (dst == 3) ? (const float*)g_ctx : Ain;
    const float scl = (dst == 0) ? 0.125f : 1.0f;   // Q pre-scale 1/sqrt(DK)

    float c[2][8][4];
    #pragma unroll
    for (int mt = 0; mt < 2; mt++)
        #pragma unroll
        for (int nt = 0; nt < 8; nt++)
            #pragma unroll
            for (int r = 0; r < 4; r++) c[mt][nt][r] = 0.f;

    const int arow  = tid >> 1;
    const int acol8 = (tid & 1) * 8;
    const int brow  = tid >> 4;
    const int bcol8 = (tid & 15) * 8;

    const float* Ap = A + (by * 128 + arow) * Dn + acol8;
    const float* Wp = W + brow * Dn + bx * 128 + bcol8;

    float4 ar0 = *(const float4*)Ap;
    float4 ar1 = *(const float4*)(Ap + 4);
    float4 wr0 = *(const float4*)Wp;
    float4 wr1 = *(const float4*)(Wp + 4);
    Ap += 16; Wp += (size_t)16 * Dn;

    storeAfrag(sA[0], arow, acol8,     ar0);
    storeAfrag(sA[0], arow, acol8 + 4, ar1);
    storeBfrag(sB[0], brow, bcol8,     wr0);
    storeBfrag(sB[0], brow, bcol8 + 4, wr1);
    __syncthreads();

    const int NIT = Dn / 16;
    for (int it = 0; it < NIT; it++) {
        const int  p    = it & 1;
        const bool more = (it + 1 < NIT);
        if (more) {
            ar0 = *(const float4*)Ap;
            ar1 = *(const float4*)(Ap + 4);
            wr0 = *(const float4*)Wp;
            wr1 = *(const float4*)(Wp + 4);
            Ap += 16; Wp += (size_t)16 * Dn;
        }

        #pragma unroll
        for (int kt = 0; kt < 2; kt++) {
            uint32_t af[2][4];
            uint32_t bf[8][2];
            #pragma unroll
            for (int mt = 0; mt < 2; mt++)
                *(uint4*)af[mt] =
                    *(const uint4*)&sA[p][(((wm * 2 + mt) * 2 + kt) << 7) + la];
            #pragma unroll
            for (int nt = 0; nt < 8; nt++) {
                const int ntile = (wn * 8 + nt) * 2 + kt;
                const int swz   = ((ntile & 3) << 1) | (((ntile >> 2) & 3) << 3);
                *(uint2*)bf[nt] =
                    *(const uint2*)&sB[p][ntile * 64 + ((lane << 1) ^ swz)];
            }
            #pragma unroll
            for (int mt = 0; mt < 2; mt++)
                #pragma unroll
                for (int nt = 0; nt < 8; nt++)
                    MMA_TF32(c[mt][nt], af[mt], bf[nt]);
        }

        if (more) {
            storeAfrag(sA[p ^ 1], arow, acol8,     ar0);
            storeAfrag(sA[p ^ 1], arow, acol8 + 4, ar1);
            storeBfrag(sB[p ^ 1], brow, bcol8,     wr0);
            storeBfrag(sB[p ^ 1], brow, bcol8 + 4, wr1);
            __syncthreads();
        }
    }

    #pragma unroll
    for (int mt = 0; mt < 2; mt++) {
        const int m0 = by * 128 + wm * 32 + mt * 16 + gid;
        #pragma unroll
        for (int nt = 0; nt < 8; nt++) {
            const int n = bx * 128 + wn * 64 + nt * 8 + tig * 2;
            const float b0v = bias[n], b1v = bias[n + 1];
            if (split) {
                float2 v0 = { tf32r((c[mt][nt][0] + b0v) * scl),
                              tf32r((c[mt][nt][1] + b1v) * scl) };
                float2 v1 = { tf32r((c[mt][nt][2] + b0v) * scl),
                              tf32r((c[mt][nt][3] + b1v) * scl) };
                const int h  = n >> 6;
                const int dk = n & 63;
                const int b0i = m0 >> 11, s0 = m0 & (Sn - 1);
                *(float2*)&Out[((b0i * Hn + h) * Sn + s0) * DKn + dk] = v0;
                const int m1 = m0 + 8;
                const int b1i = m1 >> 11, s1 = m1 & (Sn - 1);
                *(float2*)&Out[((b1i * Hn + h) * Sn + s1) * DKn + dk] = v1;
            } else {
                float2 v0 = { c[mt][nt][0] + b0v, c[mt][nt][1] + b1v };
                float2 v1 = { c[mt][nt][2] + b0v, c[mt][nt][3] + b1v };
                *(float2*)&Out[m0 * Dn + n]       = v0;
                *(float2*)&Out[(m0 + 8) * Dn + n] = v1;
            }
        }
    }
}

// ---------------------------------------------------------------------------
// FA2-style flash attention with cp.async double-buffered K/V/mask stages.
// Inputs arrive pre-rounded (and Q pre-scaled) from the GEMM epilogues, so
// tiles are ingested raw. S/P in registers; in-register online softmax.
// ---------------------------------------------------------------------------
#define STG (64 * LD + 64 * LDV + 64)   /* stage stride in floats: K + V + mask */

__device__ __forceinline__ void prefetch_tile(
    float* Ks, float* Vs, int* mk,
    const float* __restrict__ Kg, const float* __restrict__ Vg,
    const int* __restrict__ mrow, int kk0, int tid)
{
    const int r  = tid >> 2;
    const int c4 = (tid & 3) * 16;
    const float* kp = &Kg[(size_t)(kk0 + r) * DKn + c4];
    const float* vp = &Vg[(size_t)(kk0 + r) * DKn + c4];
    #pragma unroll
    for (int u = 0; u < 16; u += 4) {
        CP16(s2u(&Ks[r * LD  + c4 + u]), kp + u);
        CP16(s2u(&Vs[r * LDV + c4 + u]), vp + u);
    }
    if (tid < 16) CP16(s2u(&mk[tid * 4]), &mrow[kk0 + tid * 4]);
}

__global__ __launch_bounds__(256, 2) void flash_attn(const int* __restrict__ mask)
{
    extern __shared__ float sm[];
    float* Qs = sm;                      // [QT][LD]
    float* KsS[2]; float* VsS[2]; int* mkS[2];
    #pragma unroll
    for (int p = 0; p < 2; p++) {
        float* base = sm + QT * LD + p * STG;
        KsS[p] = base;
        VsS[p] = base + 64 * LD;
        mkS[p] = (int*)(base + 64 * LD + 64 * LDV);
    }

    const int tid = threadIdx.x;
    const int qt  = blockIdx.x;
    const int h   = blockIdx.y;
    const int b   = blockIdx.z;
    const int q0  = qt * QT;

    const int lane = tid & 31;
    const int gid  = lane >> 2;
    const int tig  = lane & 3;
    const int row0 = (tid >> 5) * 16 + gid;

    const float* Qg = g_Q + ((size_t)(b * Hn + h) * Sn + q0) * DKn;
    const float* Kg = g_K + (size_t)(b * Hn + h) * Sn * DKn;
    const float* Vg = g_V + (size_t)(b * Hn + h) * Sn * DKn;
    const int*   mrow = mask + (size_t)b * Sn;

    // Q tile: raw copy (already tf32 + scaled)
    {
        const int r   = tid >> 1;
        const int c32 = (tid & 1) * 32;
        #pragma unroll
        for (int u = 0; u < 32; u += 4)
            *(float4*)&Qs[r * LD + c32 + u] = *(const float4*)&Qg[r * DKn + c32 + u];
    }

    prefetch_tile(KsS[0], VsS[0], mkS[0], Kg, Vg, mrow, 0, tid);
    CP_COMMIT();

    float m0 = -1e30f, m1 = -1e30f, l0 = 0.f, l1 = 0.f;
    float o[8][4];
    #pragma unroll
    for (int nt = 0; nt < 8; nt++)
        #pragma unroll
        for (int r = 0; r < 4; r++) o[nt][r] = 0.f;

    const int NT = Sn / 64;
    for (int kt = 0; kt < NT; kt++) {
        const int p = kt & 1;
        if (kt + 1 < NT) {
            prefetch_tile(KsS[p ^ 1], VsS[p ^ 1], mkS[p ^ 1],
                          Kg, Vg, mrow, (kt + 1) * 64, tid);
            CP_COMMIT();
            CP_WAIT(1);
        } else {
            CP_WAIT(0);
        }
        __syncthreads();

        const float* Ks = KsS[p];
        const float* Vs = VsS[p];
        const int*   mk = mkS[p];

        // S = Q @ K^T : warp computes its 16 rows x 64 cols (8 n-tiles)
        float s[8][4];
        #pragma unroll
        for (int nt = 0; nt < 8; nt++)
            #pragma unroll
            for (int r = 0; r < 4; r++) s[nt][r] = 0.f;

        #pragma unroll
        for (int ks = 0; ks < 8; ks++) {
            const int kk = ks * 8;
            uint32_t a[4];
            const float* Ap = &Qs[row0 * LD + kk + tig];
            a[0] = __float_as_uint(Ap[0]);
            a[1] = __float_as_uint(Ap[8 * LD]);
            a[2] = __float_as_uint(Ap[4]);
            a[3] = __float_as_uint(Ap[8 * LD + 4]);
            #pragma unroll
            for (int nt = 0; nt < 8; nt++) {
                uint32_t bb[2];
                const float* Bp = &Ks[(nt * 8 + gid) * LD + kk + tig];
                bb[0] = __float_as_uint(Bp[0]);
                bb[1] = __float_as_uint(Bp[4]);
                MMA_TF32(s[nt], a, bb);
            }
        }

        // In-register online softmax
        float mx0 = -1e30f, mx1 = -1e30f;
        #pragma unroll
        for (int nt = 0; nt < 8; nt++) {
            const int mk0v = mk[nt * 8 + 2 * tig];
            const int mk1v = mk[nt * 8 + 2 * tig + 1];
            if (mk0v == 0) { s[nt][0] = -1e30f; s[nt][2] = -1e30f; }
            if (mk1v == 0) { s[nt][1] = -1e30f; s[nt][3] = -1e30f; }
            mx0 = fmaxf(mx0, fmaxf(s[nt][0], s[nt][1]));
            mx1 = fmaxf(mx1, fmaxf(s[nt][2], s[nt][3]));
        }
        mx0 = fmaxf(mx0, __shfl_xor_sync(0xffffffffu, mx0, 1));
        mx0 = fmaxf(mx0, __shfl_xor_sync(0xffffffffu, mx0, 2));
        mx1 = fmaxf(mx1, __shfl_xor_sync(0xffffffffu, mx1, 1));
        mx1 = fmaxf(mx1, __shfl_xor_sync(0xffffffffu, mx1, 2));

        const float mn0 = fmaxf(m0, mx0);
        const float mn1 = fmaxf(m1, mx1);
        const float f0  = __expf(m0 - mn0);
        const float f1  = __expf(m1 - mn1);
        m0 = mn0; m1 = mn1;

        float sum0 = 0.f, sum1 = 0.f;
        #pragma unroll
        for (int nt = 0; nt < 8; nt++) {
            float p0 = (s[nt][0] <= -1e29f) ? 0.f : tf32r(__expf(s[nt][0] - mn0));
            float p1 = (s[nt][1] <= -1e29f) ? 0.f : tf32r(__expf(s[nt][1] - mn0));
            float p2 = (s[nt][2] <= -1e29f) ? 0.f : tf32r(__expf(s[nt][2] - mn1));
            float p3 = (s[nt][3] <= -1e29f) ? 0.f : tf32r(__expf(s[nt][3] - mn1));
            s[nt][0] = p0; s[nt][1] = p1; s[nt][2] = p2; s[nt][3] = p3;
            sum0 += p0 + p1;
            sum1 += p2 + p3;
        }
        sum0 += __shfl_xor_sync(0xffffffffu, sum0, 1);
        sum0 += __shfl_xor_sync(0xffffffffu, sum0, 2);
        sum1 += __shfl_xor_sync(0xffffffffu, sum1, 1);
        sum1 += __shfl_xor_sync(0xffffffffu, sum1, 2);
        l0 = l0 * f0 + sum0;
        l1 = l1 * f1 + sum1;

        #pragma unroll
        for (int nt = 0; nt < 8; nt++) {
            o[nt][0] *= f0; o[nt][1] *= f0;
            o[nt][2] *= f1; o[nt][3] *= f1;
        }

        // O += P @ V (P C-frag -> A-frag via shuffles)
        {
            const int srcA = (lane & ~3) | (tig >> 1);
            const int srcB = srcA + 2;
            const bool odd = (tig & 1) != 0;
            #pragma unroll
            for (int ks = 0; ks < 8; ks++) {
                const float v00 = __shfl_sync(0xffffffffu, s[ks][0], srcA);
                const float v01 = __shfl_sync(0xffffffffu, s[ks][1], srcA);
                const float v02 = __shfl_sync(0xffffffffu, s[ks][2], srcA);
                const float v03 = __shfl_sync(0xffffffffu, s[ks][3], srcA);
                const float v10 = __shfl_sync(0xffffffffu, s[ks][0], srcB);
                const float v11 = __shfl_sync(0xffffffffu, s[ks][1], srcB);
                const float v12 = __shfl_sync(0xffffffffu, s[ks][2], srcB);
                const float v13 = __shfl_sync(0xffffffffu, s[ks][3], srcB);
                uint32_t a[4];
                a[0] = __float_as_uint(odd ? v01 : v00);
                a[1] = __float_as_uint(odd ? v03 : v02);
                a[2] = __float_as_uint(odd ? v11 : v10);
                a[3] = __float_as_uint(odd ? v13 : v12);

                const int kk = ks * 8;
                #pragma unroll
                for (int nt = 0; nt < 8; nt++) {
                    uint32_t bb[2];
                    const float* Bp = &Vs[(kk + tig) * LDV + nt * 8 + gid];
                    bb[0] = __float_as_uint(Bp[0]);
                    bb[1] = __float_as_uint(Bp[4 * LDV]);
                    MMA_TF32(o[nt], a, bb);
                }
            }
        }
        __syncthreads();
    }

    // Normalize and write ctx in (B,S,D) layout
    {
        const float inv0 = 1.f / l0;
        const float inv1 = 1.f / l1;
        #pragma unroll
        for (int nt = 0; nt < 8; nt++) {
            const int col = h * DKn + nt * 8 + tig * 2;
            float2 v0 = { o[nt][0] * inv0, o[nt][1] * inv0 };
            float2 v1 = { o[nt][2] * inv1, o[nt][3] * inv1 };
            *(float2*)&g_ctx[(size_t)(b * Sn + q0 + row0) * Dn + col]     = v0;
            *(float2*)&g_ctx[(size_t)(b * Sn + q0 + row0 + 8) * Dn + col] = v1;
        }
    }
}

// ---------------------------------------------------------------------------
extern "C" void kernel_launch(void* const* d_in, const int* in_sizes, int n_in,
                              void* d_out, int out_size)
{
    const float* q    = (const float*)d_in[0];
    const float* k    = (const float*)d_in[1];
    const float* v    = (const float*)d_in[2];
    const int*   mask = (const int*)  d_in[3];
    const float* Wq   = (const float*)d_in[4];
    const float* bq   = (const float*)d_in[5];
    const float* Wk   = (const float*)d_in[6];
    const float* bk   = (const float*)d_in[7];
    const float* Wv   = (const float*)d_in[8];
    const float* bv   = (const float*)d_in[9];
    const float* Wo   = (const float*)d_in[10];
    const float* bo   = (const float*)d_in[11];
    float* out = (float*)d_out;

    const dim3 gg(Dn / 128, Mn / 128);
    gemm_tf32<<<gg, 256>>>(q, Wq, bq, nullptr, 0);
    gemm_tf32<<<gg, 256>>>(k, Wk, bk, nullptr, 1);
    gemm_tf32<<<gg, 256>>>(v, Wv, bv, nullptr, 2);

    const int smem = (QT * LD + 2 * STG) * (int)sizeof(float);   // 106,880 B
    (void)cudaFuncSetAttribute(flash_attn, cudaFuncAttributeMaxDynamicSharedMemorySize, smem);
    const dim3 ga(Sn / QT, Hn, Bn);
    flash_attn<<<ga, 256, smem>>>(mask);

    gemm_tf32<<<gg, 256>>>(nullptr, Wo, bo, out, 3);
}

// round 11
// speedup vs baseline: 1.0692x; 1.0692x over previous
#include <cuda_runtime.h>
#include <math.h>
#include <stdint.h>

#define Bn 4
#define Sn 2048
#define Dn 1024
#define Hn 16
#define DKn 64
#define Mn (Bn*Sn)   /* 8192 */
#define LD 68        /* smem row stride: Q/K tiles (row-pattern conflict-free) */
#define LDV 72       /* smem row stride: V tile (column-pattern conflict-free) */
#define QT 128       /* q-tile rows per CTA in flash attention */

// Scratch (device globals: allocation-free per harness rules)
// g_Q: tf32-rounded AND pre-scaled by 1/sqrt(DK); g_K/g_V: tf32-rounded.
__device__ float g_Q[Bn*Hn*Sn*DKn];
__device__ float g_K[Bn*Hn*Sn*DKn];
__device__ float g_V[Bn*Hn*Sn*DKn];
__device__ float g_ctx[Mn*Dn];

__device__ __forceinline__ uint32_t f2tf(float f) {
    uint32_t u;
    asm("cvt.rna.tf32.f32 %0, %1;" : "=r"(u) : "f"(f));
    return u;
}
__device__ __forceinline__ float tf32r(float f) { return __uint_as_float(f2tf(f)); }

#define MMA_TF32(c, a, b) asm volatile( \
    "mma.sync.aligned.m16n8k8.row.col.f32.tf32.tf32.f32 " \
    "{%0,%1,%2,%3}, {%4,%5,%6,%7}, {%8,%9}, {%0,%1,%2,%3};\n" \
    : "+f"((c)[0]), "+f"((c)[1]), "+f"((c)[2]), "+f"((c)[3]) \
    : "r"((a)[0]), "r"((a)[1]), "r"((a)[2]), "r"((a)[3]), \
      "r"((b)[0]), "r"((b)[1]))

// ---------------------------------------------------------------------------
// tf32 tensor-core GEMM (R8-proven core). Epilogue emits tf32-rounded
// (and, for Q, pre-scaled) values for the split destinations so flash can
// consume them raw. Numerics of the full pipeline verified bit-identical.
// ---------------------------------------------------------------------------
__device__ __forceinline__ void storeAfrag(uint32_t* sA, int arow, int k4, float4 v) {
    const int kt  = k4 >> 3;
    const int reg = (((arow & 15) >= 8) ? 1 : 0) | ((k4 & 4) ? 2 : 0);
    const int a7  = arow & 7;
    const int swz = ((a7 >> 1) & 3) << 2;
    const int base = (((arow >> 4) * 2 + kt) << 7) + (a7 << 4) + reg;
    sA[(base + 0)  ^ swz] = f2tf(v.x);
    sA[(base + 4)  ^ swz] = f2tf(v.y);
    sA[(base + 8)  ^ swz] = f2tf(v.z);
    sA[(base + 12) ^ swz] = f2tf(v.w);
}

__device__ __forceinline__ void storeBfrag(uint32_t* sB, int krow, int n4, float4 v) {
    const int kt    = krow >> 3;
    const int reg   = ((krow & 7) >= 4) ? 1 : 0;
    const int ntile = (n4 >> 3) * 2 + kt;
    const int swz   = ((ntile & 3) << 1) | (((ntile >> 2) & 3) << 3);
    const int base  = ntile * 64 + (n4 & 7) * 8 + (krow & 3) * 2 + reg;
    sB[(base + 0)  ^ swz] = f2tf(v.x);
    sB[(base + 8)  ^ swz] = f2tf(v.y);
    sB[(base + 16) ^ swz] = f2tf(v.z);
    sB[(base + 24) ^ swz] = f2tf(v.w);
}

__global__ __launch_bounds__(256) void gemm_tf32(
    const float* __restrict__ Ain, const float* __restrict__ W,
    const float* __restrict__ bias, float* __restrict__ OutP, int dst)
{
    __shared__ uint32_t sA[2][2048];
    __shared__ uint32_t sB[2][2048];

    const int tid  = threadIdx.x;
    const int bx   = blockIdx.x;
    const int by   = blockIdx.y;
    const int wid  = tid >> 5;
    const int lane = tid & 31;
    const int wm   = wid & 3;
    const int wn   = wid >> 2;
    const int gid  = lane >> 2;
    const int tig  = lane & 3;
    const int la   = (lane << 2) ^ (((lane >> 3) & 3) << 2);

    float* Out;
    bool   split;
    if      (dst == 0) { Out = g_Q;  split = true;  }
    else if (dst == 1) { Out = g_K;  split = true;  }
    else if (dst == 2) { Out = g_V;  split = true;  }
    else               { Out = OutP; split = false; }
    const float* A = (dst == 3) ? (const float*)g_ctx : Ain;
    const float scl = (dst == 0) ? 0.125f : 1.0f;   // Q pre-scale 1/sqrt(DK)

    float c[2][8][4];
    #pragma unroll
    for (int mt = 0; mt < 2; mt++)
        #pragma unroll
        for (int nt = 0; nt < 8; nt++)
            #pragma unroll
            for (int r = 0; r < 4; r++) c[mt][nt][r] = 0.f;

    const int arow  = tid >> 1;
    const int acol8 = (tid & 1) * 8;
    const int brow  = tid >> 4;
    const int bcol8 = (tid & 15) * 8;

    const float* Ap = A + (by * 128 + arow) * Dn + acol8;
    const float* Wp = W + brow * Dn + bx * 128 + bcol8;

    float4 ar0 = *(const float4*)Ap;
    float4 ar1 = *(const float4*)(Ap + 4);
    float4 wr0 = *(const float4*)Wp;
    float4 wr1 = *(const float4*)(Wp + 4);
    Ap += 16; Wp += (size_t)16 * Dn;

    storeAfrag(sA[0], arow, acol8,     ar0);
    storeAfrag(sA[0], arow, acol8 + 4, ar1);
    storeBfrag(sB[0], brow, bcol8,     wr0);
    storeBfrag(sB[0], brow, bcol8 + 4, wr1);
    __syncthreads();

    const int NIT = Dn / 16;
    for (int it = 0; it < NIT; it++) {
        const int  p    = it & 1;
        const bool more = (it + 1 < NIT);
        if (more) {
            ar0 = *(const float4*)Ap;
            ar1 = *(const float4*)(Ap + 4);
            wr0 = *(const float4*)Wp;
            wr1 = *(const float4*)(Wp + 4);
            Ap += 16; Wp += (size_t)16 * Dn;
        }

        #pragma unroll
        for (int kt = 0; kt < 2; kt++) {
            uint32_t af[2][4];
            uint32_t bf[8][2];
            #pragma unroll
            for (int mt = 0; mt < 2; mt++)
                *(uint4*)af[mt] =
                    *(const uint4*)&sA[p][(((wm * 2 + mt) * 2 + kt) << 7) + la];
            #pragma unroll
            for (int nt = 0; nt < 8; nt++) {
                const int ntile = (wn * 8 + nt) * 2 + kt;
                const int swz   = ((ntile & 3) << 1) | (((ntile >> 2) & 3) << 3);
                *(uint2*)bf[nt] =
                    *(const uint2*)&sB[p][ntile * 64 + ((lane << 1) ^ swz)];
            }
            #pragma unroll
            for (int mt = 0; mt < 2; mt++)
                #pragma unroll
                for (int nt = 0; nt < 8; nt++)
                    MMA_TF32(c[mt][nt], af[mt], bf[nt]);
        }

        if (more) {
            storeAfrag(sA[p ^ 1], arow, acol8,     ar0);
            storeAfrag(sA[p ^ 1], arow, acol8 + 4, ar1);
            storeBfrag(sB[p ^ 1], brow, bcol8,     wr0);
            storeBfrag(sB[p ^ 1], brow, bcol8 + 4, wr1);
            __syncthreads();
        }
    }

    #pragma unroll
    for (int mt = 0; mt < 2; mt++) {
        const int m0 = by * 128 + wm * 32 + mt * 16 + gid;
        #pragma unroll
        for (int nt = 0; nt < 8; nt++) {
            const int n = bx * 128 + wn * 64 + nt * 8 + tig * 2;
            const float b0v = bias[n], b1v = bias[n + 1];
            if (split) {
                float2 v0 = { tf32r((c[mt][nt][0] + b0v) * scl),
                              tf32r((c[mt][nt][1] + b1v) * scl) };
                float2 v1 = { tf32r((c[mt][nt][2] + b0v) * scl),
                              tf32r((c[mt][nt][3] + b1v) * scl) };
                const int h  = n >> 6;
                const int dk = n & 63;
                const int b0i = m0 >> 11, s0 = m0 & (Sn - 1);
                *(float2*)&Out[((b0i * Hn + h) * Sn + s0) * DKn + dk] = v0;
                const int m1 = m0 + 8;
                const int b1i = m1 >> 11, s1 = m1 & (Sn - 1);
                *(float2*)&Out[((b1i * Hn + h) * Sn + s1) * DKn + dk] = v1;
            } else {
                float2 v0 = { c[mt][nt][0] + b0v, c[mt][nt][1] + b1v };
                float2 v1 = { c[mt][nt][2] + b0v, c[mt][nt][3] + b1v };
                *(float2*)&Out[m0 * Dn + n]       = v0;
                *(float2*)&Out[(m0 + 8) * Dn + n] = v1;
            }
        }
    }
}

// ---------------------------------------------------------------------------
// FA2-style flash attention (R9-proven structure: synchronous LDG->STS tile
// loads, 2 barriers per k-tile). Inputs arrive pre-rounded (Q pre-scaled)
// from the GEMM epilogues, so tile loads are raw float4 copies — no cvt.
// S/P in registers; in-register online softmax; P->A-frag via shuffles.
// ---------------------------------------------------------------------------
__global__ __launch_bounds__(256, 2) void flash_attn(const int* __restrict__ mask)
{
    extern __shared__ float sm[];
    float* Qs  = sm;                        // [QT][LD]  Q (tf32 bits, scaled)
    float* Ks  = sm + QT * LD;              // [64][LD]  K
    float* Vs  = sm + QT * LD + 64 * LD;    // [64][LDV] V
    float* msk = Vs + 64 * LDV;             // [64]

    const int tid = threadIdx.x;
    const int qt  = blockIdx.x;
    const int h   = blockIdx.y;
    const int b   = blockIdx.z;
    const int q0  = qt * QT;

    const int lane = tid & 31;
    const int gid  = lane >> 2;
    const int tig  = lane & 3;
    const int row0 = (tid >> 5) * 16 + gid;

    const float* Qg = g_Q + ((size_t)(b * Hn + h) * Sn + q0) * DKn;
    const float* Kg = g_K + (size_t)(b * Hn + h) * Sn * DKn;
    const float* Vg = g_V + (size_t)(b * Hn + h) * Sn * DKn;

    // Q tile: raw copy (already tf32 + scaled); each thread one half-row
    {
        const int r   = tid >> 1;
        const int c32 = (tid & 1) * 32;
        #pragma unroll
        for (int u = 0; u < 32; u += 4)
            *(float4*)&Qs[r * LD + c32 + u] = *(const float4*)&Qg[r * DKn + c32 + u];
    }

    float m0 = -1e30f, m1 = -1e30f, l0 = 0.f, l1 = 0.f;
    float o[8][4];
    #pragma unroll
    for (int nt = 0; nt < 8; nt++)
        #pragma unroll
        for (int r = 0; r < 4; r++) o[nt][r] = 0.f;

    for (int kt = 0; kt < Sn / 64; kt++) {
        const int kk0 = kt * 64;

        // K and V tiles: raw float4 copies, mask flags
        {
            const int r  = tid >> 2;
            const int c4 = (tid & 3) * 16;
            #pragma unroll
            for (int u = 0; u < 16; u += 4)
                *(float4*)&Ks[r * LD + c4 + u] =
                    *(const float4*)&Kg[(size_t)(kk0 + r) * DKn + c4 + u];
            #pragma unroll
            for (int u = 0; u < 16; u += 4)
                *(float4*)&Vs[r * LDV + c4 + u] =
                    *(const float4*)&Vg[(size_t)(kk0 + r) * DKn + c4 + u];
        }
        if (tid < 64) msk[tid] = (mask[b * Sn + kk0 + tid] == 0) ? 1.f : 0.f;
        __syncthreads();

        // S = Q @ K^T : warp computes its 16 rows x 64 cols (8 n-tiles)
        float s[8][4];
        #pragma unroll
        for (int nt = 0; nt < 8; nt++)
            #pragma unroll
            for (int r = 0; r < 4; r++) s[nt][r] = 0.f;

        #pragma unroll
        for (int ks = 0; ks < 8; ks++) {
            const int kk = ks * 8;
            uint32_t a[4];
            const float* Ap = &Qs[row0 * LD + kk + tig];
            a[0] = __float_as_uint(Ap[0]);
            a[1] = __float_as_uint(Ap[8 * LD]);
            a[2] = __float_as_uint(Ap[4]);
            a[3] = __float_as_uint(Ap[8 * LD + 4]);
            #pragma unroll
            for (int nt = 0; nt < 8; nt++) {
                uint32_t bb[2];
                const float* Bp = &Ks[(nt * 8 + gid) * LD + kk + tig];
                bb[0] = __float_as_uint(Bp[0]);
                bb[1] = __float_as_uint(Bp[4]);
                MMA_TF32(s[nt], a, bb);
            }
        }

        // In-register online softmax
        float mx0 = -1e30f, mx1 = -1e30f;
        #pragma unroll
        for (int nt = 0; nt < 8; nt++) {
            const float mk0 = msk[nt * 8 + 2 * tig];
            const float mk1 = msk[nt * 8 + 2 * tig + 1];
            if (mk0 != 0.f) { s[nt][0] = -1e30f; s[nt][2] = -1e30f; }
            if (mk1 != 0.f) { s[nt][1] = -1e30f; s[nt][3] = -1e30f; }
            mx0 = fmaxf(mx0, fmaxf(s[nt][0], s[nt][1]));
            mx1 = fmaxf(mx1, fmaxf(s[nt][2], s[nt][3]));
        }
        mx0 = fmaxf(mx0, __shfl_xor_sync(0xffffffffu, mx0, 1));
        mx0 = fmaxf(mx0, __shfl_xor_sync(0xffffffffu, mx0, 2));
        mx1 = fmaxf(mx1, __shfl_xor_sync(0xffffffffu, mx1, 1));
        mx1 = fmaxf(mx1, __shfl_xor_sync(0xffffffffu, mx1, 2));

        const float mn0 = fmaxf(m0, mx0);
        const float mn1 = fmaxf(m1, mx1);
        const float f0  = __expf(m0 - mn0);
        const float f1  = __expf(m1 - mn1);
        m0 = mn0; m1 = mn1;

        float sum0 = 0.f, sum1 = 0.f;
        #pragma unroll
        for (int nt = 0; nt < 8; nt++) {
            float p0 = (s[nt][0] <= -1e29f) ? 0.f : tf32r(__expf(s[nt][0] - mn0));
            float p1 = (s[nt][1] <= -1e29f) ? 0.f : tf32r(__expf(s[nt][1] - mn0));
            float p2 = (s[nt][2] <= -1e29f) ? 0.f : tf32r(__expf(s[nt][2] - mn1));
            float p3 = (s[nt][3] <= -1e29f) ? 0.f : tf32r(__expf(s[nt][3] - mn1));
            s[nt][0] = p0; s[nt][1] = p1; s[nt][2] = p2; s[nt][3] = p3;
            sum0 += p0 + p1;
            sum1 += p2 + p3;
        }
        sum0 += __shfl_xor_sync(0xffffffffu, sum0, 1);
        sum0 += __shfl_xor_sync(0xffffffffu, sum0, 2);
        sum1 += __shfl_xor_sync(0xffffffffu, sum1, 1);
        sum1 += __shfl_xor_sync(0xffffffffu, sum1, 2);
        l0 = l0 * f0 + sum0;
        l1 = l1 * f1 + sum1;

        // Rescale O
        #pragma unroll
        for (int nt = 0; nt < 8; nt++) {
            o[nt][0] *= f0; o[nt][1] *= f0;
            o[nt][2] *= f1; o[nt][3] *= f1;
        }

        // O += P @ V (P C-frag -> A-frag via shuffles)
        {
            const int srcA = (lane & ~3) | (tig >> 1);
            const int srcB = srcA + 2;
            const bool odd = (tig & 1) != 0;
            #pragma unroll
            for (int ks = 0; ks < 8; ks++) {
                const float v00 = __shfl_sync(0xffffffffu, s[ks][0], srcA);
                const float v01 = __shfl_sync(0xffffffffu, s[ks][1], srcA);
                const float v02 = __shfl_sync(0xffffffffu, s[ks][2], srcA);
                const float v03 = __shfl_sync(0xffffffffu, s[ks][3], srcA);
                const float v10 = __shfl_sync(0xffffffffu, s[ks][0], srcB);
                const float v11 = __shfl_sync(0xffffffffu, s[ks][1], srcB);
                const float v12 = __shfl_sync(0xffffffffu, s[ks][2], srcB);
                const float v13 = __shfl_sync(0xffffffffu, s[ks][3], srcB);
                uint32_t a[4];
                a[0] = __float_as_uint(odd ? v01 : v00);   // P[gid   ][kk+tig]
                a[1] = __float_as_uint(odd ? v03 : v02);   // P[gid+8 ][kk+tig]
                a[2] = __float_as_uint(odd ? v11 : v10);   // P[gid   ][kk+tig+4]
                a[3] = __float_as_uint(odd ? v13 : v12);   // P[gid+8 ][kk+tig+4]

                const int kk = ks * 8;
                #pragma unroll
                for (int nt = 0; nt < 8; nt++) {
                    uint32_t bb[2];
                    const float* Bp = &Vs[(kk + tig) * LDV + nt * 8 + gid];
                    bb[0] = __float_as_uint(Bp[0]);
                    bb[1] = __float_as_uint(Bp[4 * LDV]);
                    MMA_TF32(o[nt], a, bb);
                }
            }
        }
        __syncthreads();
    }

    // Normalize and write ctx in (B,S,D) layout
    {
        const float inv0 = 1.f / l0;
        const float inv1 = 1.f / l1;
        #pragma unroll
        for (int nt = 0; nt < 8; nt++) {
            const int col = h * DKn + nt * 8 + tig * 2;
            float2 v0 = { o[nt][0] * inv0, o[nt][1] * inv0 };
            float2 v1 = { o[nt][2] * inv1, o[nt][3] * inv1 };
            *(float2*)&g_ctx[(size_t)(b * Sn + q0 + row0) * Dn + col]     = v0;
            *(float2*)&g_ctx[(size_t)(b * Sn + q0 + row0 + 8) * Dn + col] = v1;
        }
    }
}

// ---------------------------------------------------------------------------
extern "C" void kernel_launch(void* const* d_in, const int* in_sizes, int n_in,
                              void* d_out, int out_size)
{
    const float* q    = (const float*)d_in[0];
    const float* k    = (const float*)d_in[1];
    const float* v    = (const float*)d_in[2];
    const int*   mask = (const int*)  d_in[3];
    const float* Wq   = (const float*)d_in[4];
    const float* bq   = (const float*)d_in[5];
    const float* Wk   = (const float*)d_in[6];
    const float* bk   = (const float*)d_in[7];
    const float* Wv   = (const float*)d_in[8];
    const float* bv   = (const float*)d_in[9];
    const float* Wo   = (const float*)d_in[10];
    const float* bo   = (const float*)d_in[11];
    float* out = (float*)d_out;

    const dim3 gg(Dn / 128, Mn / 128);
    gemm_tf32<<<gg, 256>>>(q, Wq, bq, nullptr, 0);
    gemm_tf32<<<gg, 256>>>(k, Wk, bk, nullptr, 1);
    gemm_tf32<<<gg, 256>>>(v, Wv, bv, nullptr, 2);

    const int smem = (QT * LD + 64 * LD + 64 * LDV + 64) * (int)sizeof(float); // 70912 B
    (void)cudaFuncSetAttribute(flash_attn, cudaFuncAttributeMaxDynamicSharedMemorySize, smem);
    const dim3 ga(Sn / QT, Hn, Bn);
    flash_attn<<<ga, 256, smem>>>(mask);

    gemm_tf32<<<gg, 256>>>(nullptr, Wo, bo, out, 3);
}